// round 4
// baseline (speedup 1.0000x reference)
#include <cuda_runtime.h>
#include <math.h>

#define HW   4096
#define NJ   17
#define NL   16
#define BV   16           // bs*nv
#define NMH  (BV*NJ)      // 272 heatmap maps
#define NMF  (BV*NL)      // 256 field maps
#define KSZ  127
#define BETA_ 100.0f

// output layout (concatenated, row-major, tuple order)
// kps_combined: 4*4*17*2     = 544
// comb_v:       4*4*16*3     = 768
// comb_p:       4*4*16*2     = 512
// fields_new:   4*4*16*3*4096= 3145728
// hms_new:      4*4*17*4096  = 1114112
#define OFF_KPS 0
#define OFF_CV  544
#define OFF_CP  1312
#define OFF_FN  1824
#define OFF_HMS 3147552

__device__ float g_K[2*KSZ*KSZ];
__device__ float g_hm_c[NMH*HW];
__device__ float g_std_hm[NMH];
__device__ float g_s[NMF];
__device__ float g_fds[NMF*HW];
__device__ float g_kps[NMH*2];
__device__ float g_kpn[NMH*2];

__constant__ int c_P0[16]    = {0,1,2,0,4,5,0,7,8,9,8,11,12,8,14,15};
__constant__ int c_proxL[17] = {6,1,2,-1,4,5,-1,7,13,9,-1,11,12,-1,14,15,-1};
// distL[j] = j-1 (j>=1), -1 for j==0 (computed inline)

// ---------------- reductions (256 threads) ----------------
__device__ __forceinline__ float bsum(float v, float* red){
    __syncthreads();
    #pragma unroll
    for (int o=16;o;o>>=1) v += __shfl_down_sync(0xffffffffu, v, o);
    if ((threadIdx.x & 31)==0) red[threadIdx.x>>5] = v;
    __syncthreads();
    float r = 0.f;
    #pragma unroll
    for (int k=0;k<8;k++) r += red[k];
    return r;
}
__device__ __forceinline__ float bmax(float v, float* red){
    __syncthreads();
    #pragma unroll
    for (int o=16;o;o>>=1) v = fmaxf(v, __shfl_down_sync(0xffffffffu, v, o));
    if ((threadIdx.x & 31)==0) red[threadIdx.x>>5] = v;
    __syncthreads();
    float r = red[0];
    #pragma unroll
    for (int k=1;k<8;k++) r = fmaxf(r, red[k]);
    return r;
}

// ---------------- kernel table ----------------
__global__ void k_init(){
    int idx = blockIdx.x*blockDim.x + threadIdx.x;
    if (idx < KSZ*KSZ){
        int i = idx / KSZ, j = idx % KSZ;
        float a = 64.f - (float)j;      // ker[0]
        float b = 64.f - (float)i;      // ker[1]
        float d2 = a*a + b*b;
        if (i==64 && j==64) d2 = 1.f;
        g_K[idx]           = a / d2;
        g_K[KSZ*KSZ + idx] = b / d2;
    }
}

// ---------------- heatmap center + std (ddof=1) ----------------
__global__ __launch_bounds__(256) void k_hm_center(const float* __restrict__ hm){
    __shared__ float s[HW];
    __shared__ float red[8];
    int m = blockIdx.x;
    const float* src = hm + (size_t)m*HW;
    float sum = 0.f;
    for (int i=threadIdx.x;i<HW;i+=256){ float v = src[i]; s[i]=v; sum += v; }
    sum = bsum(sum, red);
    float mean = sum * (1.f/HW);
    float ss = 0.f;
    for (int i=threadIdx.x;i<HW;i+=256){ float v = s[i]-mean; g_hm_c[(size_t)m*HW+i]=v; ss += v*v; }
    ss = bsum(ss, red);
    if (threadIdx.x==0) g_std_hm[m] = sqrtf(ss/(float)(HW-1));
}

// ---------------- field stats: std_df scale, lvecs (comb_v), lpts (comb_p) ----------------
__global__ __launch_bounds__(256) void k_field_stats(const float* __restrict__ fields,
                                                     const int* __restrict__ ishape,
                                                     float* __restrict__ out){
    __shared__ float fn[HW];
    __shared__ float red[8];
    int m = blockIdx.x;
    const float* f0 = fields + (size_t)m*3*HW;
    const float* f1 = f0 + HW;
    const float* f2 = f0 + 2*HW;
    float sum=0.f, ss=0.f, lv0=0.f, lv1=0.f, lv2=0.f, mx=-1e30f;
    for (int i=threadIdx.x;i<HW;i+=256){
        float a=f0[i], b=f1[i], c=f2[i];
        sum += a+b+c;
        float q = a*a+b*b+c*c;
        ss += q;
        float n = sqrtf(q);
        fn[i]=n;
        lv0 += n*a; lv1 += n*b; lv2 += n*c;
        mx = fmaxf(mx, n);
    }
    sum = bsum(sum, red); ss = bsum(ss, red);
    lv0 = bsum(lv0, red); lv1 = bsum(lv1, red); lv2 = bsum(lv2, red);
    mx  = bmax(mx, red);
    float Z=0.f, Si=0.f, Sj=0.f;
    for (int i=threadIdx.x;i<HW;i+=256){
        float e = expf((fn[i]-mx)*BETA_);
        Z += e; Si += e*(float)(i>>6); Sj += e*(float)(i&63);
    }
    Z = bsum(Z, red); Si = bsum(Si, red); Sj = bsum(Sj, red);
    if (threadIdx.x==0){
        const float N = 3.f*HW;
        float var = (ss - sum*sum/N) / (N-1.f);
        float st  = sqrtf(fmaxf(var, 0.f));
        g_s[m] = st/(st+1e-6f);
        float nrm = sqrtf(lv0*lv0+lv1*lv1+lv2*lv2);
        float dn  = fmaxf(nrm, 1e-12f);
        out[OFF_CV + m*3+0] = lv0/dn;
        out[OFF_CV + m*3+1] = lv1/dn;
        out[OFF_CV + m*3+2] = lv2/dn;
        float sx = (float)ishape[1] * (1.f/64.f);
        float sy = (float)ishape[0] * (1.f/64.f);
        out[OFF_CP + m*2+0] = Si/Z*sx;
        out[OFF_CP + m*2+1] = Sj/Z*sy;
    }
}

// ---------------- conv1 (flipped kernel) + coef + fields_new ----------------
// convs[o][y,x] = sum_{py,px} Hs[py,px] * K[o][y-py+63][x-px+63]
__global__ __launch_bounds__(256) void k_conv1(const float* __restrict__ fields,
                                               float* __restrict__ out){
    __shared__ float Is[HW];
    __shared__ float Ks[2][128];
    int blk = blockIdx.x;
    int m = blk >> 2, strip = blk & 3;
    int bv = m >> 4, l = m & 15;
    const float* hA = g_hm_c + (size_t)(bv*NJ + (l+1))*HW;      // P1[l] = l+1
    const float* hB = g_hm_c + (size_t)(bv*NJ + c_P0[l])*HW;
    for (int i=threadIdx.x;i<HW;i+=256) Is[i] = hA[i]-hB[i];

    int ty = threadIdx.x >> 4, tx = threadIdx.x & 15;
    int y  = strip*16 + ty;
    int x0 = tx*4;
    float a0=0,a1=0,a2=0,a3=0, b0=0,b1=0,b2=0,b3=0;

    int tlo = strip*16;
    int thi = min(127, strip*16 + 79);
    for (int t=tlo; t<thi; ++t){
        __syncthreads();
        if (threadIdx.x < 254){
            int c = threadIdx.x/127, u = threadIdx.x - c*127;
            Ks[c][u] = g_K[c*KSZ*KSZ + t*KSZ + u];
        }
        __syncthreads();
        int py = y + 63 - t;
        if ((unsigned)py < 64u){
            const float* ir = &Is[py<<6];
            const float* k0 = &Ks[0][x0+63];
            const float* k1 = &Ks[1][x0+63];
            #pragma unroll 8
            for (int px=0;px<64;++px){
                float iv = ir[px];
                a0 += iv*k0[ 0-px]; a1 += iv*k0[1-px]; a2 += iv*k0[2-px]; a3 += iv*k0[3-px];
                b0 += iv*k1[ 0-px]; b1 += iv*k1[1-px]; b2 += iv*k1[2-px]; b3 += iv*k1[3-px];
            }
        }
    }
    // epilogue: coef = relu(conv0*f0 + conv1*f1), fields_new = fields*coef
    const float* fb = fields + (size_t)m*3*HW;
    float* ob = out + OFF_FN + (size_t)m*3*HW;
    int idx = (y<<6) + x0;
    float ca[4] = {a0,a1,a2,a3};
    float cb[4] = {b0,b1,b2,b3};
    #pragma unroll
    for (int i=0;i<4;++i){
        float f0v = fb[idx+i], f1v = fb[HW+idx+i], f2v = fb[2*HW+idx+i];
        float coef = fmaxf(0.f, ca[i]*f0v + cb[i]*f1v);
        ob[idx+i]        = f0v*coef;
        ob[HW+idx+i]     = f1v*coef;
        ob[2*HW+idx+i]   = f2v*coef;
    }
}

// ---------------- conv2 (unflipped kernel) on scaled fields -> g_fds ----------------
// fds[y,x] = sum_c sum_{py,px} (s*F[c,py,px]) * K[c][py-y+63][px-x+63]
__global__ __launch_bounds__(256) void k_conv2(const float* __restrict__ fields){
    __shared__ float Is[2][HW];
    __shared__ float Ks[2][128];
    int blk = blockIdx.x;
    int m = blk >> 2, strip = blk & 3;
    float sc = g_s[m];
    const float* f0 = fields + (size_t)m*3*HW;
    for (int i=threadIdx.x;i<HW;i+=256){ Is[0][i]=f0[i]*sc; Is[1][i]=f0[HW+i]*sc; }

    int ty = threadIdx.x >> 4, tx = threadIdx.x & 15;
    int y  = strip*16 + ty;
    int x0 = tx*4;
    float a0=0,a1=0,a2=0,a3=0;

    int tlo = max(0, 48 - strip*16);
    int thi = 127 - strip*16;           // exclusive
    for (int t=tlo; t<thi; ++t){
        __syncthreads();
        if (threadIdx.x < 254){
            int c = threadIdx.x/127, u = threadIdx.x - c*127;
            Ks[c][u] = g_K[c*KSZ*KSZ + t*KSZ + u];
        }
        __syncthreads();
        int py = y + t - 63;
        if ((unsigned)py < 64u){
            const float* i0 = &Is[0][py<<6];
            const float* i1 = &Is[1][py<<6];
            const float* k0 = &Ks[0][63 - x0];
            const float* k1 = &Ks[1][63 - x0];
            #pragma unroll 8
            for (int px=0;px<64;++px){
                float u0 = i0[px], u1 = i1[px];
                a0 += u0*k0[px  ] + u1*k1[px  ];
                a1 += u0*k0[px-1] + u1*k1[px-1];
                a2 += u0*k0[px-2] + u1*k1[px-2];
                a3 += u0*k0[px-3] + u1*k1[px-3];
            }
        }
    }
    float* gb = g_fds + (size_t)m*HW;
    int idx = (y<<6) + x0;
    gb[idx+0]=a0; gb[idx+1]=a1; gb[idx+2]=a2; gb[idx+3]=a3;
}

// ---------------- hms_new: multipliers + normalize ----------------
__global__ __launch_bounds__(256) void k_hms(float* __restrict__ out){
    __shared__ float s[HW];
    __shared__ float red[8];
    int mb = blockIdx.x;
    int bv = mb / NJ, j = mb - bv*NJ;
    const float* hm = g_hm_c + (size_t)mb*HW;
    int pl = c_proxL[j];
    int dl = j - 1;                       // -1 for j==0
    const float* fp = (pl>=0) ? g_fds + (size_t)(bv*NL+pl)*HW : (const float*)0;
    const float* fd = (dl>=0) ? g_fds + (size_t)(bv*NL+dl)*HW : (const float*)0;
    float sum = 0.f;
    for (int i=threadIdx.x;i<HW;i+=256){
        float v = hm[i];
        if (pl>=0) v *= fmaxf(0.f, -fp[i]);
        if (dl>=0) v *= fmaxf(0.f,  fd[i]);
        s[i]=v; sum += v;
    }
    sum = bsum(sum, red);
    float mean = sum * (1.f/HW);
    float ss = 0.f;
    for (int i=threadIdx.x;i<HW;i+=256){ float d = s[i]-mean; ss += d*d; }
    ss = bsum(ss, red);
    float st = sqrtf(ss/(float)(HW-1));
    float scale = g_std_hm[mb] / (st + 1e-6f);
    float* ob = out + OFF_HMS + (size_t)mb*HW;
    for (int i=threadIdx.x;i<HW;i+=256) ob[i] = s[i]*scale;
}

// ---------------- soft_argmax (both heatmap sets) ----------------
__global__ __launch_bounds__(256) void k_softargmax(const float* __restrict__ outp,
                                                    const int* __restrict__ ishape){
    __shared__ float s[HW];
    __shared__ float red[8];
    int bid = blockIdx.x;
    const float* src; float* dst;
    if (bid < NMH){ src = g_hm_c + (size_t)bid*HW;               dst = g_kps + bid*2; }
    else          { src = outp + OFF_HMS + (size_t)(bid-NMH)*HW; dst = g_kpn + (bid-NMH)*2; }
    float mx = -1e30f;
    for (int i=threadIdx.x;i<HW;i+=256){ float v = src[i]; s[i]=v; mx = fmaxf(mx, v); }
    mx = bmax(mx, red);
    float Z=0.f, Si=0.f, Sj=0.f;
    for (int i=threadIdx.x;i<HW;i+=256){
        float e = expf((s[i]-mx)*BETA_);
        Z += e; Si += e*(float)(i>>6); Sj += e*(float)(i&63);
    }
    Z = bsum(Z, red); Si = bsum(Si, red); Sj = bsum(Sj, red);
    if (threadIdx.x==0){
        float sx = (float)ishape[1] * (1.f/64.f);
        float sy = (float)ishape[0] * (1.f/64.f);
        dst[0] = Si/Z*sx;
        dst[1] = Sj/Z*sy;
    }
}

// ---------------- final combine -> kps_combined ----------------
__global__ void k_combine(const float* __restrict__ confs,
                          const float* __restrict__ pth1p,
                          const float* __restrict__ pth2p,
                          float* __restrict__ out){
    int t = blockIdx.x*blockDim.x + threadIdx.x;
    if (t < NMH){
        int bv = t / NJ, j = t - bv*NJ;
        float kx = g_kps[t*2+0], ky = g_kps[t*2+1];
        float nx = g_kpn[t*2+0], ny = g_kpn[t*2+1];
        if (isnan(nx)) nx = kx;
        if (isnan(ny)) ny = ky;
        float dx = nx-kx, dy = ny-ky;
        float disp = sqrtf(dx*dx+dy*dy);
        float conf = confs[bv*(NL+NJ) + NL + j];
        bool sel = (conf > pth1p[0]) && (disp < pth2p[0]);
        out[OFF_KPS + t*2+0] = sel ? nx : kx;
        out[OFF_KPS + t*2+1] = sel ? ny : ky;
    }
}

extern "C" void kernel_launch(void* const* d_in, const int* in_sizes, int n_in,
                              void* d_out, int out_size){
    const float* heatmaps = (const float*)d_in[0];
    const float* fields   = (const float*)d_in[1];
    const int*   ishape   = (const int*)  d_in[5];
    const float* confs    = (const float*)d_in[6];
    const float* pth1     = (const float*)d_in[9];
    const float* pth2     = (const float*)d_in[10];
    float* out = (float*)d_out;

    k_init<<<127,128>>>();
    k_hm_center<<<NMH,256>>>(heatmaps);
    k_field_stats<<<NMF,256>>>(fields, ishape, out);
    k_conv1<<<NMF*4,256>>>(fields, out);
    k_conv2<<<NMF*4,256>>>(fields);
    k_hms<<<NMH,256>>>(out);
    k_softargmax<<<2*NMH,256>>>(out, ishape);
    k_combine<<<2,256>>>(confs, pth1, pth2, out);
}

// round 6
// speedup vs baseline: 1.0276x; 1.0276x over previous
#include <cuda_runtime.h>
#include <math.h>

#define HW   4096
#define NJ   17
#define NL   16
#define BV   16           // bs*nv
#define NMH  (BV*NJ)      // 272 heatmap maps
#define NMF  (BV*NL)      // 256 field maps
#define KSZ  127
#define BETA_ 100.0f

// output layout (concatenated, row-major, tuple order)
#define OFF_KPS 0
#define OFF_CV  544
#define OFF_CP  1312
#define OFF_FN  1824
#define OFF_HMS 3147552

// padded input-tile geometry for conv kernels
#define RP 66                 // padded row length (floats or float2s)
#define TILE (64*RP + RP)     // 64 rows + 1 zero row

typedef unsigned long long u64;

__device__ float2 g_Kt2[KSZ*KSZ];    // interleaved (K0,K1)
__device__ float g_hm_c[NMH*HW];
__device__ float g_std_hm[NMH];
__device__ float g_s[NMF];
__device__ float g_fds[NMF*HW];
__device__ float g_kps[NMH*2];
__device__ float g_kpn[NMH*2];

__constant__ int c_P0[16]    = {0,1,2,0,4,5,0,7,8,9,8,11,12,8,14,15};
__constant__ int c_proxL[17] = {6,1,2,-1,4,5,-1,7,13,9,-1,11,12,-1,14,15,-1};

// ---------------- f32x2 helpers ----------------
__device__ __forceinline__ u64 dup2(float x){
    u64 r; asm("mov.b64 %0, {%1, %2};" : "=l"(r) : "f"(x), "f"(x)); return r;
}
__device__ __forceinline__ void fma2(u64& d, u64 a, u64 b){
    asm("fma.rn.f32x2 %0, %1, %2, %0;" : "+l"(d) : "l"(a), "l"(b));
}
__device__ __forceinline__ void unpack2(u64 v, float& x, float& y){
    asm("mov.b64 {%0, %1}, %2;" : "=f"(x), "=f"(y) : "l"(v));
}

// ---------------- reductions (256 threads) ----------------
__device__ __forceinline__ float bsum(float v, float* red){
    __syncthreads();
    #pragma unroll
    for (int o=16;o;o>>=1) v += __shfl_down_sync(0xffffffffu, v, o);
    if ((threadIdx.x & 31)==0) red[threadIdx.x>>5] = v;
    __syncthreads();
    float r = 0.f;
    #pragma unroll
    for (int k=0;k<8;k++) r += red[k];
    return r;
}
__device__ __forceinline__ float bmax(float v, float* red){
    __syncthreads();
    #pragma unroll
    for (int o=16;o;o>>=1) v = fmaxf(v, __shfl_down_sync(0xffffffffu, v, o));
    if ((threadIdx.x & 31)==0) red[threadIdx.x>>5] = v;
    __syncthreads();
    float r = red[0];
    #pragma unroll
    for (int k=1;k<8;k++) r = fmaxf(r, red[k]);
    return r;
}

// ---------------- kernel table (interleaved) ----------------
__global__ void k_init(){
    int idx = blockIdx.x*blockDim.x + threadIdx.x;
    if (idx < KSZ*KSZ){
        int i = idx / KSZ, j = idx % KSZ;
        float a = 64.f - (float)j;      // ker[0]
        float b = 64.f - (float)i;      // ker[1]
        float d2 = a*a + b*b;
        if (i==64 && j==64) d2 = 1.f;
        g_Kt2[idx] = make_float2(a/d2, b/d2);
    }
}

// ---------------- heatmap center + std (ddof=1) ----------------
__global__ __launch_bounds__(256) void k_hm_center(const float* __restrict__ hm){
    __shared__ float s[HW];
    __shared__ float red[8];
    int m = blockIdx.x;
    const float* src = hm + (size_t)m*HW;
    float sum = 0.f;
    for (int i=threadIdx.x;i<HW;i+=256){ float v = src[i]; s[i]=v; sum += v; }
    sum = bsum(sum, red);
    float mean = sum * (1.f/HW);
    float ss = 0.f;
    for (int i=threadIdx.x;i<HW;i+=256){ float v = s[i]-mean; g_hm_c[(size_t)m*HW+i]=v; ss += v*v; }
    ss = bsum(ss, red);
    if (threadIdx.x==0) g_std_hm[m] = sqrtf(ss/(float)(HW-1));
}

// ---------------- field stats ----------------
__global__ __launch_bounds__(256) void k_field_stats(const float* __restrict__ fields,
                                                     const int* __restrict__ ishape,
                                                     float* __restrict__ out){
    __shared__ float fn[HW];
    __shared__ float red[8];
    int m = blockIdx.x;
    const float* f0 = fields + (size_t)m*3*HW;
    const float* f1 = f0 + HW;
    const float* f2 = f0 + 2*HW;
    float sum=0.f, ss=0.f, lv0=0.f, lv1=0.f, lv2=0.f, mx=-1e30f;
    for (int i=threadIdx.x;i<HW;i+=256){
        float a=f0[i], b=f1[i], c=f2[i];
        sum += a+b+c;
        float q = a*a+b*b+c*c;
        ss += q;
        float n = sqrtf(q);
        fn[i]=n;
        lv0 += n*a; lv1 += n*b; lv2 += n*c;
        mx = fmaxf(mx, n);
    }
    sum = bsum(sum, red); ss = bsum(ss, red);
    lv0 = bsum(lv0, red); lv1 = bsum(lv1, red); lv2 = bsum(lv2, red);
    mx  = bmax(mx, red);
    float Z=0.f, Si=0.f, Sj=0.f;
    for (int i=threadIdx.x;i<HW;i+=256){
        float e = expf((fn[i]-mx)*BETA_);
        Z += e; Si += e*(float)(i>>6); Sj += e*(float)(i&63);
    }
    Z = bsum(Z, red); Si = bsum(Si, red); Sj = bsum(Sj, red);
    if (threadIdx.x==0){
        const float N = 3.f*HW;
        float var = (ss - sum*sum/N) / (N-1.f);
        float st  = sqrtf(fmaxf(var, 0.f));
        g_s[m] = st/(st+1e-6f);
        float nrm = sqrtf(lv0*lv0+lv1*lv1+lv2*lv2);
        float dn  = fmaxf(nrm, 1e-12f);
        out[OFF_CV + m*3+0] = lv0/dn;
        out[OFF_CV + m*3+1] = lv1/dn;
        out[OFF_CV + m*3+2] = lv2/dn;
        float sx = (float)ishape[1] * (1.f/64.f);
        float sy = (float)ishape[0] * (1.f/64.f);
        out[OFF_CP + m*2+0] = Si/Z*sx;
        out[OFF_CP + m*2+1] = Sj/Z*sy;
    }
}

// ---------------- conv1 (flipped kernel) via FFMA2, ch0/ch1 packed ----------------
// convs[o][y,x] = sum_{py,px} Hs[py,px] * K[o][y-py+63][x-px+63];  py = y+63-t
// Block: 2 maps, 8 warps = 2 maps x 4 strips. Thread: 4 rows (j) x 8 cols (i, stride 8).
__global__ __launch_bounds__(256) void k_conv1(const float* __restrict__ fields,
                                               float* __restrict__ out){
    __shared__ float Is[2][TILE];
    __shared__ float2 Kt[8][128];
    int bm = blockIdx.x;          // 0..127
    int tid = threadIdx.x;

    // stage Hs for both maps into padded layout
    #pragma unroll
    for (int g=0; g<2; ++g){
        int m = bm*2 + g;
        int bv = m >> 4, l = m & 15;
        const float* hA = g_hm_c + (size_t)(bv*NJ + (l+1))*HW;   // P1[l] = l+1
        const float* hB = g_hm_c + (size_t)(bv*NJ + c_P0[l])*HW;
        for (int idx=tid; idx<HW; idx+=256){
            int r = idx>>6, c = idx&63;
            Is[g][r*RP + c] = hA[idx]-hB[idx];
        }
    }
    for (int idx=tid; idx<2*RP; idx+=256)
        Is[idx/RP][64*RP + idx%RP] = 0.f;   // zero row

    int w    = tid >> 5, lane = tid & 31;
    int g    = w >> 2,  s    = w & 3;
    int ty   = lane >> 3, tx = lane & 7;
    int m    = bm*2 + g;
    int y0   = s*16 + ty*4;
    int tlo  = s*16, thi = min(126, s*16+78);
    const float* zr = &Is[g][64*RP];

    u64 acc[4][8];
    #pragma unroll
    for (int j=0;j<4;++j)
        #pragma unroll
        for (int i=0;i<8;++i) acc[j][i] = 0ull;

    for (int tc=0; tc<16; ++tc){
        __syncthreads();
        for (int idx=tid; idx<8*127; idx+=256){
            int tt = idx/127, u = idx - tt*127;
            int t = tc*8 + tt;
            if (t < 127) Kt[tt][u] = g_Kt2[t*127 + u];
        }
        __syncthreads();
        if (tc*8 > thi || tc*8+7 < tlo) continue;
        #pragma unroll 1
        for (int tt=0; tt<8; ++tt){
            int t = tc*8 + tt;
            if (t > 126) break;
            if (t < tlo || t > thi) continue;
            const float* rp[4];
            #pragma unroll
            for (int j=0;j<4;++j){
                int py = y0 + j + 63 - t;
                rp[j] = ((unsigned)py < 64u) ? &Is[g][py*RP] : zr;
            }
            const float2* Kr = Kt[tt];
            #pragma unroll 2
            for (int px2=0; px2<32; ++px2){
                int px = px2*2;
                u64 ax[4], ay[4];
                #pragma unroll
                for (int j=0;j<4;++j){
                    float2 iv = *(const float2*)(rp[j] + px);
                    ax[j] = dup2(iv.x); ay[j] = dup2(iv.y);
                }
                #pragma unroll
                for (int i=0;i<8;++i){
                    int wb = tx + 8*i + 62 - px;
                    u64 kb = *(const u64*)(Kr + wb);        // for px+1
                    u64 ka = *(const u64*)(Kr + wb + 1);    // for px
                    #pragma unroll
                    for (int j=0;j<4;++j){
                        fma2(acc[j][i], ax[j], ka);
                        fma2(acc[j][i], ay[j], kb);
                    }
                }
            }
        }
    }
    // epilogue: coef = relu(convA*f0 + convB*f1)
    const float* fb = fields + (size_t)m*3*HW;
    float* ob = out + OFF_FN + (size_t)m*3*HW;
    #pragma unroll
    for (int j=0;j<4;++j)
        #pragma unroll
        for (int i=0;i<8;++i){
            int idx = (y0+j)*64 + tx + 8*i;
            float cA, cB; unpack2(acc[j][i], cA, cB);
            float f0v = fb[idx], f1v = fb[HW+idx], f2v = fb[2*HW+idx];
            float coef = fmaxf(0.f, cA*f0v + cB*f1v);
            ob[idx]      = f0v*coef;
            ob[HW+idx]   = f1v*coef;
            ob[2*HW+idx] = f2v*coef;
        }
}

// ---------------- conv2 (unflipped) via FFMA2, input-channel pair packed ----------------
// fds[y,x] = sum_c sum_{py,px} (s*F[c,py,px]) * K[c][py-y+63][px-x+63];  py = y+t-63
__global__ __launch_bounds__(256) void k_conv2(const float* __restrict__ fields){
    extern __shared__ float2 dsm[];
    float2* If2 = dsm;               // [2][TILE]
    float2* Kt  = dsm + 2*TILE;      // [8][128]
    int bm = blockIdx.x;
    int tid = threadIdx.x;

    #pragma unroll
    for (int g=0; g<2; ++g){
        int m = bm*2 + g;
        float sc = g_s[m];
        const float* f0 = fields + (size_t)m*3*HW;
        const float* f1 = f0 + HW;
        for (int idx=tid; idx<HW; idx+=256){
            int r = idx>>6, c = idx&63;
            If2[g*TILE + r*RP + c] = make_float2(sc*f0[idx], sc*f1[idx]);
        }
    }
    for (int idx=tid; idx<2*RP; idx+=256)
        If2[(idx/RP)*TILE + 64*RP + idx%RP] = make_float2(0.f, 0.f);

    int w    = tid >> 5, lane = tid & 31;
    int g    = w >> 2,  s    = w & 3;
    int ty   = lane >> 3, tx = lane & 7;
    int m    = bm*2 + g;
    int y0   = s*16 + ty*4;
    int tlo  = max(0, 48 - s*16), thi = 126 - s*16;
    const float2* zr = &If2[g*TILE + 64*RP];

    u64 acc[4][8];
    #pragma unroll
    for (int j=0;j<4;++j)
        #pragma unroll
        for (int i=0;i<8;++i) acc[j][i] = 0ull;

    for (int tc=0; tc<16; ++tc){
        __syncthreads();
        for (int idx=tid; idx<8*127; idx+=256){
            int tt = idx/127, u = idx - tt*127;
            int t = tc*8 + tt;
            if (t < 127) Kt[tt*128 + u] = g_Kt2[t*127 + u];
        }
        __syncthreads();
        if (tc*8 > thi || tc*8+7 < tlo) continue;
        #pragma unroll 1
        for (int tt=0; tt<8; ++tt){
            int t = tc*8 + tt;
            if (t > 126) break;
            if (t < tlo || t > thi) continue;
            const float2* rp[4];
            #pragma unroll
            for (int j=0;j<4;++j){
                int py = y0 + j + t - 63;
                rp[j] = ((unsigned)py < 64u) ? &If2[g*TILE + py*RP] : zr;
            }
            const float2* Kr = &Kt[tt*128];
            #pragma unroll 2
            for (int px2=0; px2<32; ++px2){
                int px = px2*2;
                u64 iva[4], ivb[4];
                #pragma unroll
                for (int j=0;j<4;++j){
                    ulonglong2 q = *(const ulonglong2*)(rp[j] + px);
                    iva[j] = q.x; ivb[j] = q.y;
                }
                #pragma unroll
                for (int i=0;i<8;++i){
                    int wb = px - (tx + 8*i) + 63;
                    u64 ka = *(const u64*)(Kr + wb);        // for px
                    u64 kb = *(const u64*)(Kr + wb + 1);    // for px+1
                    #pragma unroll
                    for (int j=0;j<4;++j){
                        fma2(acc[j][i], iva[j], ka);
                        fma2(acc[j][i], ivb[j], kb);
                    }
                }
            }
        }
    }
    float* gb = g_fds + (size_t)m*HW;
    #pragma unroll
    for (int j=0;j<4;++j)
        #pragma unroll
        for (int i=0;i<8;++i){
            float c0, c1; unpack2(acc[j][i], c0, c1);
            gb[(y0+j)*64 + tx + 8*i] = c0 + c1;
        }
}

// ---------------- hms_new: multipliers + normalize ----------------
__global__ __launch_bounds__(256) void k_hms(float* __restrict__ out){
    __shared__ float s[HW];
    __shared__ float red[8];
    int mb = blockIdx.x;
    int bv = mb / NJ, j = mb - bv*NJ;
    const float* hm = g_hm_c + (size_t)mb*HW;
    int pl = c_proxL[j];
    int dl = j - 1;
    const float* fp = (pl>=0) ? g_fds + (size_t)(bv*NL+pl)*HW : (const float*)0;
    const float* fd = (dl>=0) ? g_fds + (size_t)(bv*NL+dl)*HW : (const float*)0;
    float sum = 0.f;
    for (int i=threadIdx.x;i<HW;i+=256){
        float v = hm[i];
        if (pl>=0) v *= fmaxf(0.f, -fp[i]);
        if (dl>=0) v *= fmaxf(0.f,  fd[i]);
        s[i]=v; sum += v;
    }
    sum = bsum(sum, red);
    float mean = sum * (1.f/HW);
    float ss = 0.f;
    for (int i=threadIdx.x;i<HW;i+=256){ float d = s[i]-mean; ss += d*d; }
    ss = bsum(ss, red);
    float st = sqrtf(ss/(float)(HW-1));
    float scale = g_std_hm[mb] / (st + 1e-6f);
    float* ob = out + OFF_HMS + (size_t)mb*HW;
    for (int i=threadIdx.x;i<HW;i+=256) ob[i] = s[i]*scale;
}

// ---------------- soft_argmax (both heatmap sets) ----------------
__global__ __launch_bounds__(256) void k_softargmax(const float* __restrict__ outp,
                                                    const int* __restrict__ ishape){
    __shared__ float s[HW];
    __shared__ float red[8];
    int bid = blockIdx.x;
    const float* src; float* dst;
    if (bid < NMH){ src = g_hm_c + (size_t)bid*HW;               dst = g_kps + bid*2; }
    else          { src = outp + OFF_HMS + (size_t)(bid-NMH)*HW; dst = g_kpn + (bid-NMH)*2; }
    float mx = -1e30f;
    for (int i=threadIdx.x;i<HW;i+=256){ float v = src[i]; s[i]=v; mx = fmaxf(mx, v); }
    mx = bmax(mx, red);
    float Z=0.f, Si=0.f, Sj=0.f;
    for (int i=threadIdx.x;i<HW;i+=256){
        float e = expf((s[i]-mx)*BETA_);
        Z += e; Si += e*(float)(i>>6); Sj += e*(float)(i&63);
    }
    Z = bsum(Z, red); Si = bsum(Si, red); Sj = bsum(Sj, red);
    if (threadIdx.x==0){
        float sx = (float)ishape[1] * (1.f/64.f);
        float sy = (float)ishape[0] * (1.f/64.f);
        dst[0] = Si/Z*sx;
        dst[1] = Sj/Z*sy;
    }
}

// ---------------- final combine -> kps_combined ----------------
__global__ void k_combine(const float* __restrict__ confs,
                          const float* __restrict__ pth1p,
                          const float* __restrict__ pth2p,
                          float* __restrict__ out){
    int t = blockIdx.x*blockDim.x + threadIdx.x;
    if (t < NMH){
        int bv = t / NJ, j = t - bv*NJ;
        float kx = g_kps[t*2+0], ky = g_kps[t*2+1];
        float nx = g_kpn[t*2+0], ny = g_kpn[t*2+1];
        if (isnan(nx)) nx = kx;
        if (isnan(ny)) ny = ky;
        float dx = nx-kx, dy = ny-ky;
        float disp = sqrtf(dx*dx+dy*dy);
        float conf = confs[bv*(NL+NJ) + NL + j];
        bool sel = (conf > pth1p[0]) && (disp < pth2p[0]);
        out[OFF_KPS + t*2+0] = sel ? nx : kx;
        out[OFF_KPS + t*2+1] = sel ? ny : ky;
    }
}

extern "C" void kernel_launch(void* const* d_in, const int* in_sizes, int n_in,
                              void* d_out, int out_size){
    const float* heatmaps = (const float*)d_in[0];
    const float* fields   = (const float*)d_in[1];
    const int*   ishape   = (const int*)  d_in[5];
    const float* confs    = (const float*)d_in[6];
    const float* pth1     = (const float*)d_in[9];
    const float* pth2     = (const float*)d_in[10];
    float* out = (float*)d_out;

    int smem2 = (2*TILE + 8*128) * (int)sizeof(float2);
    static int configured = 0;
    if (!configured){
        cudaFuncSetAttribute(k_conv2, cudaFuncAttributeMaxDynamicSharedMemorySize, smem2);
        configured = 1;
    }

    k_init<<<127,128>>>();
    k_hm_center<<<NMH,256>>>(heatmaps);
    k_field_stats<<<NMF,256>>>(fields, ishape, out);
    k_conv1<<<NMF/2,256>>>(fields, out);
    k_conv2<<<NMF/2,256,smem2>>>(fields);
    k_hms<<<NMH,256>>>(out);
    k_softargmax<<<2*NMH,256>>>(out, ishape);
    k_combine<<<2,256>>>(confs, pth1, pth2, out);
}